// round 16
// baseline (speedup 1.0000x reference)
#include <cuda_runtime.h>
#include <cuda_fp16.h>
#include <cstdint>

// ---------------- problem dims ----------------
#define BB 8
#define TT 4096
#define DD 1024
#define MM (BB*TT)        // 32768
#define NBR 2048          // interleaved B rows: row = 2*d + s (s=0 delta, 1 value)

// ---------------- GEMM tiling ----------------
#define BM 128
#define BN 128            // 64 d's (delta+value interleaved)
#define NKC 16            // 1024/64 K-chunks
#define MT (MM/BM)        // 256
#define NT (NBR/BN)       // 16

#define S_STAGES 3
#define BUF_A  0
#define BUF_B  16384
#define STAGE_BYTES 32768
#define SMEM_TOTAL (S_STAGES*STAGE_BYTES)   // 98304 -> 2 CTAs/SM

// ---------------- scan chunking: chunk == 64 t (wm granularity) ----------------
#define NCHB 64           // chunks per batch
#define NCHT 512          // total chunks (== MT*2)

// ---------------- device scratch ----------------
__device__ __align__(256) __half   g_B[(size_t)NBR*DD];     // 4 MB interleaved W
// g_ab in warp-native layout (u32 = half2(a,b)):
// idx = (((((mt*16+nt)*2+wm)*4+wn)*4+nf)*4+mf)*2+p)*32 + lane
__device__ __align__(256) uint32_t g_ab[(size_t)MM*DD];     // 128 MB
__device__ float2 g_AS[NCHT][DD];                           // chunk affine (A,S)

// ---------------- PTX helpers (family-independent only) ----------------
__device__ __forceinline__ uint32_t smem_u32(const void* p) {
    uint32_t a;
    asm("{ .reg .u64 t; cvta.to.shared.u64 t, %1; cvt.u32.u64 %0, t; }" : "=r"(a) : "l"(p));
    return a;
}
__device__ __forceinline__ void cp16(uint32_t dst, const void* src) {
    asm volatile("cp.async.cg.shared.global [%0], [%1], 16;" :: "r"(dst), "l"(src) : "memory");
}
__device__ __forceinline__ void cp_commit() {
    asm volatile("cp.async.commit_group;" ::: "memory");
}
template<int N>
__device__ __forceinline__ void cp_wait() {
    asm volatile("cp.async.wait_group %0;" :: "n"(N) : "memory");
}
__device__ __forceinline__ void ldsm4(uint32_t* r, uint32_t addr) {
    asm volatile("ldmatrix.sync.aligned.m8n8.x4.shared.b16 {%0,%1,%2,%3}, [%4];"
        : "=r"(r[0]), "=r"(r[1]), "=r"(r[2]), "=r"(r[3]) : "r"(addr));
}
__device__ __forceinline__ void mma16816(float* c, const uint32_t* a, const uint32_t* b) {
    asm volatile("mma.sync.aligned.m16n8k16.row.col.f32.f16.f16.f32 "
        "{%0,%1,%2,%3}, {%4,%5,%6,%7}, {%8,%9}, {%0,%1,%2,%3};"
        : "+f"(c[0]), "+f"(c[1]), "+f"(c[2]), "+f"(c[3])
        : "r"(a[0]), "r"(a[1]), "r"(a[2]), "r"(a[3]), "r"(b[0]), "r"(b[1]));
}
__device__ __forceinline__ float fast_sigmoid(float x) {
    float t;
    asm("tanh.approx.f32 %0, %1;" : "=f"(t) : "f"(x * 0.5f));
    return fmaf(t, 0.5f, 0.5f);
}
__device__ __forceinline__ uint4 pack8_h(const float* xs) {
    uint32_t w[8];
    #pragma unroll
    for (int i = 0; i < 8; i++)
        w[i] = (uint32_t)__half_as_ushort(__float2half_rn(xs[i]));
    return make_uint4(w[0]|(w[1]<<16), w[2]|(w[3]<<16), w[4]|(w[5]<<16), w[6]|(w[7]<<16));
}

// ---------------- conversion: B only (A converts inside the GEMM loader) ----
// B: interleave rows — g_B row r = 2*d+s <- (s ? Wv : Wd)[d]
__global__ __launch_bounds__(256) void conv_B(const float* __restrict__ Wd,
                                              const float* __restrict__ Wv)
{
    size_t gid = (size_t)blockIdx.x * 256 + threadIdx.x;   // NBR*DD/8 = 262144
    int r  = (int)(gid >> 7);        // 0..2047
    int k0 = ((int)gid & 127) * 8;
    int d  = r >> 1, s = r & 1;
    const float* src = (s ? Wv : Wd) + (size_t)d * DD + k0;
    float4 x0 = *(const float4*)src;
    float4 x1 = *(const float4*)(src + 4);
    float xs[8] = {x0.x, x0.y, x0.z, x0.w, x1.x, x1.y, x1.z, x1.w};
    *(uint4*)(g_B + (size_t)r * DD + k0) = pack8_h(xs);
}

// ---------------- GEMM (A: fp32 LDG+cvt+STS; B: cp.async) + fused epilogue ---
__global__ void __launch_bounds__(256, 2)
gemm_mma(const float* __restrict__ seq,
         const float* __restrict__ bias_d, const float* __restrict__ bias_v)
{
    extern __shared__ __align__(1024) char smem[];
    const uint32_t sb = smem_u32(smem);
    const int tid = threadIdx.x;
    const int nt = blockIdx.x, mt = blockIdx.y;
    const int m0 = mt * BM;

    const float* gAf = seq + (size_t)m0 * DD;               // fp32 A source
    const char*  gB  = (const char*)(g_B + (size_t)nt * BN * DD);

    // loader mapping (fixed per thread): 4 units, unit = (row, u)
    int lrow[4], lu[4];
    uint32_t lphys[4];
    #pragma unroll
    for (int i = 0; i < 4; i++) {
        int uid = i * 256 + tid;           // 0..1023
        lrow[i] = uid >> 3; lu[i] = uid & 7;
        lphys[i] = (uint32_t)(lrow[i] * 128 + (((lu[i] ^ (lrow[i] & 7)) << 4)));
    }

    // A: synchronous fp32 load -> fp16 convert -> STS (grouped LDGs for MLP=8)
    auto load_stage_A = [&](int s, int c) {
        char* st = smem + s * STAGE_BYTES + BUF_A;
        float4 ra[4], rb[4];
        #pragma unroll
        for (int i = 0; i < 4; i++) {
            const float* src = gAf + (size_t)lrow[i] * DD + c * 64 + lu[i] * 8;
            ra[i] = *(const float4*)src;
            rb[i] = *(const float4*)(src + 4);
        }
        #pragma unroll
        for (int i = 0; i < 4; i++) {
            float xs[8] = {ra[i].x, ra[i].y, ra[i].z, ra[i].w,
                           rb[i].x, rb[i].y, rb[i].z, rb[i].w};
            *(uint4*)(st + lphys[i]) = pack8_h(xs);
        }
    };
    // B: async bulk copy (pre-swizzled fp16)
    auto load_stage_B = [&](int s, int c) {
        uint32_t st = sb + s * STAGE_BYTES + BUF_B;
        #pragma unroll
        for (int i = 0; i < 4; i++) {
            size_t gofs = (size_t)lrow[i] * (DD * 2) + (size_t)c * 128 + (size_t)lu[i] * 16;
            cp16(st + lphys[i], gB + gofs);
        }
    };

    // ---- compute mapping: 8 warps in 2(m) x 4(n); warp tile 64x32 ----
    const int lane = tid & 31, wid = tid >> 5;
    const int wm = wid >> 2, wn = wid & 3;

    const int arow  = lane & 15;
    const int ahalf = lane >> 4;
    const int brow  = (lane & 7) | (((lane >> 4) & 1) << 3);
    const int bhalf = (lane >> 3) & 1;
    const int swA   = arow & 7;
    const int swB   = brow & 7;

    uint32_t aRowOff[4], bRowOff[2];
    #pragma unroll
    for (int mf = 0; mf < 4; mf++) aRowOff[mf] = (uint32_t)((wm * 64 + mf * 16 + arow) * 128);
    #pragma unroll
    for (int np = 0; np < 2; np++) bRowOff[np] = (uint32_t)((wn * 32 + np * 16 + brow) * 128);

    float acc[4][4][4] = {};

    // ---- pipeline prologue (3 stages) ----
    load_stage_A(0, 0); load_stage_B(0, 0); cp_commit();
    load_stage_A(1, 1); load_stage_B(1, 1); cp_commit();
    load_stage_A(2, 2); load_stage_B(2, 2); cp_commit();

    #pragma unroll 1
    for (int c = 0; c < NKC; c++) {
        cp_wait<2>();
        __syncthreads();

        const int s = c % S_STAGES;
        const uint32_t st = sb + s * STAGE_BYTES;
        #pragma unroll
        for (int kk = 0; kk < 4; kk++) {
            const uint32_t aun = (uint32_t)(((kk * 2 + ahalf) ^ swA) << 4);
            const uint32_t bun = (uint32_t)(((kk * 2 + bhalf) ^ swB) << 4);
            uint32_t ah[4][4], bh[4][2];
            #pragma unroll
            for (int mf = 0; mf < 4; mf++)
                ldsm4(ah[mf], st + BUF_A + aRowOff[mf] + aun);
            #pragma unroll
            for (int np = 0; np < 2; np++) {
                uint32_t r[4];
                ldsm4(r, st + BUF_B + bRowOff[np] + bun);
                bh[np*2+0][0] = r[0]; bh[np*2+0][1] = r[1];
                bh[np*2+1][0] = r[2]; bh[np*2+1][1] = r[3];
            }
            #pragma unroll
            for (int mf = 0; mf < 4; mf++)
                #pragma unroll
                for (int nf = 0; nf < 4; nf++)
                    mma16816(acc[mf][nf], ah[mf], bh[nf]);
        }
        __syncthreads();
        if (c + 3 < NKC) { load_stage_A(c % S_STAGES, c + 3); load_stage_B(c % S_STAGES, c + 3); }
        cp_commit();
    }

    // ==== fused epilogue ====
    const int dbase = nt * 64 + wn * 16 + (lane & 3);
    const int j = lane >> 2;
    uint32_t* __restrict__ wab =
        g_ab + ((((size_t)(mt * 16 + nt) * 2 + wm) * 4 + wn) * 1024) + lane;

    #pragma unroll
    for (int nf = 0; nf < 4; nf++) {
        const int dg = dbase + nf * 4;
        const float bd = bias_d[dg];
        const float bv = bias_v[dg];

        float Ca = 1.0f, Cb = 0.0f;          // running chunk (64 t) composition
        #pragma unroll
        for (int mf = 0; mf < 4; mf++) {
            #pragma unroll
            for (int p = 0; p < 2; p++) {    // (mf,p) ascending == t ascending
                float dh = acc[mf][nf][p*2+0] + bd;
                float vh = acc[mf][nf][p*2+1] + bv;
                float del = fast_sigmoid(dh);
                float a = 1.0f - del;
                float b = del * vh;
                __half2 h = __floats2half2_rn(a, b);
                wab[(((nf * 4 + mf) * 2 + p) << 5)] = *(uint32_t*)&h;  // coalesced
                // ordered butterfly over j (lane bits 2..4): product of 8 t's
                float Wa = a, Wb = b;
                #pragma unroll
                for (int mk = 4; mk <= 16; mk <<= 1) {
                    float oa = __shfl_xor_sync(0xffffffffu, Wa, mk);
                    float ob = __shfl_xor_sync(0xffffffffu, Wb, mk);
                    if (lane & mk) {         // self upper: self ∘ other
                        Wb = fmaf(Wa, ob, Wb);
                        Wa = Wa * oa;
                    } else {                 // other upper: other ∘ self
                        Wb = fmaf(oa, Wb, ob);
                        Wa = oa * Wa;
                    }
                }
                Cb = fmaf(Wa, Cb, Wb);
                Ca = Wa * Ca;
            }
        }
        if (j == 0)                          // lanes 0..3 publish dd 0..3
            g_AS[mt * 2 + wm][dg] = make_float2(Ca, Cb);
    }
}

// ---------------- scan: fused carry-prefix + chunk replay (R12 champion) -----
// grid (NCHB, BB, 4) x 128 threads: each CTA owns 256 d-channels of one chunk.
__global__ __launch_bounds__(128) void scan_fused(float* __restrict__ out)
{
    const int x = blockIdx.x;          // chunk within batch: 0..63
    const int b = blockIdx.y;
    const int q = blockIdx.z;          // d-slice: 0..3 (256 d each)
    const int mt = b * 32 + (x >> 1), wm = x & 1;
    const int tid = threadIdx.x;       // 0..127; handles d2 = q*256 + tid*2, +1
    const int d2 = q * 256 + tid * 2;
    const int ntp = d2 >> 6, rem = d2 & 63;
    const int wnp = rem >> 4, nfp = (rem >> 2) & 3, lo = rem & 3;   // lo in {0,2}

    // ---- carry-in: prefix-apply maps 0..x-1 of this batch ----
    float2 cur = make_float2(0.f, 0.f);
    {
        const int ch0 = b * NCHB;
        int c = 0;
        for (; c + 8 <= x; c += 8) {           // group-prefetch, MLP=8
            float4 m[8];
            #pragma unroll
            for (int k = 0; k < 8; k++)
                m[k] = *(const float4*)&g_AS[ch0 + c + k][d2];
            #pragma unroll
            for (int k = 0; k < 8; k++) {
                cur.x = fmaf(m[k].x, cur.x, m[k].y);
                cur.y = fmaf(m[k].z, cur.y, m[k].w);
            }
        }
        for (; c < x; c++) {                   // tail (<8)
            float4 m = *(const float4*)&g_AS[ch0 + c][d2];
            cur.x = fmaf(m.x, cur.x, m.y);
            cur.y = fmaf(m.z, cur.y, m.w);
        }
    }

    // ---- replay this chunk (double-buffered g_ab stream) ----
    const uint32_t* __restrict__ tb =
        g_ab + (((((size_t)(mt * 16 + ntp) * 2 + wm) * 4 + wnp) * 4 + nfp) * 256) + lo;
    const size_t obase = ((size_t)mt * BM + (size_t)wm * 64) * DD + d2;

    uint2 cbuf[8], nbuf[8];
    #pragma unroll
    for (int jj = 0; jj < 8; jj++) cbuf[jj] = *(const uint2*)(tb + jj * 4);

    #pragma unroll
    for (int g = 0; g < 8; g++) {              // segment g = (mf*2+p)
        if (g < 7) {
            const uint32_t* seg = tb + (g + 1) * 32;
            #pragma unroll
            for (int jj = 0; jj < 8; jj++) nbuf[jj] = *(const uint2*)(seg + jj * 4);
        }
        float* op = out + obase + (size_t)(g * 8) * DD;
        #pragma unroll
        for (int jj = 0; jj < 8; jj++) {
            float2 p0 = __half22float2(*(__half2*)&cbuf[jj].x);
            float2 p1 = __half22float2(*(__half2*)&cbuf[jj].y);
            cur.x = fmaf(p0.x, cur.x, p0.y);
            cur.y = fmaf(p1.x, cur.y, p1.y);
            *(float2*)(op + (size_t)jj * DD) = cur;
        }
        #pragma unroll
        for (int jj = 0; jj < 8; jj++) cbuf[jj] = nbuf[jj];
    }
}

// ---------------- launch ----------------
extern "C" void kernel_launch(void* const* d_in, const int* in_sizes, int n_in,
                              void* d_out, int out_size)
{
    const float* seq = (const float*)d_in[0];
    const float* Wd  = (const float*)d_in[1];
    const float* bd  = (const float*)d_in[2];
    const float* Wv  = (const float*)d_in[3];
    const float* bv  = (const float*)d_in[4];
    float* out = (float*)d_out;

    cudaFuncSetAttribute(gemm_mma, cudaFuncAttributeMaxDynamicSharedMemorySize, SMEM_TOTAL);

    conv_B<<<1024, 256>>>(Wd, Wv);
    gemm_mma<<<dim3(NT, MT), 256, SMEM_TOTAL>>>(seq, bd, bv);
    scan_fused<<<dim3(NCHB, BB, 4), 128>>>(out);
}

// round 17
// speedup vs baseline: 1.4385x; 1.4385x over previous
#include <cuda_runtime.h>
#include <cuda_fp16.h>
#include <cstdint>

// ---------------- problem dims ----------------
#define BB 8
#define TT 4096
#define DD 1024
#define MM (BB*TT)        // 32768
#define NBR 2048          // interleaved B rows: row = 2*d + s (s=0 delta, 1 value)

// ---------------- GEMM tiling ----------------
#define BM 128
#define BN 128            // 64 d's (delta+value interleaved)
#define NKC 16            // 1024/64 K-chunks
#define MT (MM/BM)        // 256
#define NT (NBR/BN)       // 16

#define S_STAGES 3
#define BUF_A  0
#define BUF_B  16384
#define STAGE_BYTES 32768
#define SMEM_TOTAL (S_STAGES*STAGE_BYTES)   // 98304 -> 2 CTAs/SM

// ---------------- scan chunking: chunk == 64 t (wm granularity) ----------------
#define NCHB 64           // chunks per batch
#define NCHT 512          // total chunks (== MT*2)

// ---------------- device scratch ----------------
__device__ __align__(256) __half   g_A[(size_t)MM*DD];      // 64 MB fp16 A
__device__ __align__(256) __half   g_B[(size_t)NBR*DD];     // 4 MB interleaved W
// g_ab in warp-native layout (u32 = half2(a,b)):
// idx = (((((mt*16+nt)*2+wm)*4+wn)*4+nf)*4+mf)*2+p)*32 + lane
__device__ __align__(256) uint32_t g_ab[(size_t)MM*DD];     // 128 MB
__device__ float2 g_AS[NCHT][DD];                           // chunk affine (A,S)

// ---------------- PTX helpers (family-independent only) ----------------
__device__ __forceinline__ uint32_t smem_u32(const void* p) {
    uint32_t a;
    asm("{ .reg .u64 t; cvta.to.shared.u64 t, %1; cvt.u32.u64 %0, t; }" : "=r"(a) : "l"(p));
    return a;
}
__device__ __forceinline__ void cp16(uint32_t dst, const void* src) {
    asm volatile("cp.async.cg.shared.global [%0], [%1], 16;" :: "r"(dst), "l"(src) : "memory");
}
__device__ __forceinline__ void cp_commit() {
    asm volatile("cp.async.commit_group;" ::: "memory");
}
template<int N>
__device__ __forceinline__ void cp_wait() {
    asm volatile("cp.async.wait_group %0;" :: "n"(N) : "memory");
}
__device__ __forceinline__ void ldsm4(uint32_t* r, uint32_t addr) {
    asm volatile("ldmatrix.sync.aligned.m8n8.x4.shared.b16 {%0,%1,%2,%3}, [%4];"
        : "=r"(r[0]), "=r"(r[1]), "=r"(r[2]), "=r"(r[3]) : "r"(addr));
}
__device__ __forceinline__ void mma16816(float* c, const uint32_t* a, const uint32_t* b) {
    asm volatile("mma.sync.aligned.m16n8k16.row.col.f32.f16.f16.f32 "
        "{%0,%1,%2,%3}, {%4,%5,%6,%7}, {%8,%9}, {%0,%1,%2,%3};"
        : "+f"(c[0]), "+f"(c[1]), "+f"(c[2]), "+f"(c[3])
        : "r"(a[0]), "r"(a[1]), "r"(a[2]), "r"(a[3]), "r"(b[0]), "r"(b[1]));
}
__device__ __forceinline__ float fast_sigmoid(float x) {
    float t;
    asm("tanh.approx.f32 %0, %1;" : "=f"(t) : "f"(x * 0.5f));
    return fmaf(t, 0.5f, 0.5f);
}

// ---------------- conversion (separate kernels — proven config) ----------
__global__ __launch_bounds__(256) void conv_A(const float* __restrict__ seq)
{
    size_t gid = (size_t)blockIdx.x * 256 + threadIdx.x;   // MM*DD/8 threads
    size_t e0 = gid * 8;
    float4 x0 = *(const float4*)(seq + e0);
    float4 x1 = *(const float4*)(seq + e0 + 4);
    float xs[8] = {x0.x, x0.y, x0.z, x0.w, x1.x, x1.y, x1.z, x1.w};
    uint32_t w[8];
    #pragma unroll
    for (int i = 0; i < 8; i++)
        w[i] = (uint32_t)__half_as_ushort(__float2half_rn(xs[i]));
    *(uint4*)(g_A + e0) = make_uint4(w[0]|(w[1]<<16), w[2]|(w[3]<<16),
                                     w[4]|(w[5]<<16), w[6]|(w[7]<<16));
}

// B: interleave rows — g_B row r = 2*d+s <- (s ? Wv : Wd)[d]
__global__ __launch_bounds__(256) void conv_B(const float* __restrict__ Wd,
                                              const float* __restrict__ Wv)
{
    size_t gid = (size_t)blockIdx.x * 256 + threadIdx.x;   // NBR*DD/8 = 262144
    int r  = (int)(gid >> 7);        // 0..2047
    int k0 = ((int)gid & 127) * 8;
    int d  = r >> 1, s = r & 1;
    const float* src = (s ? Wv : Wd) + (size_t)d * DD + k0;
    float4 x0 = *(const float4*)src;
    float4 x1 = *(const float4*)(src + 4);
    float xs[8] = {x0.x, x0.y, x0.z, x0.w, x1.x, x1.y, x1.z, x1.w};
    uint32_t w[8];
    #pragma unroll
    for (int i = 0; i < 8; i++)
        w[i] = (uint32_t)__half_as_ushort(__float2half_rn(xs[i]));
    *(uint4*)(g_B + (size_t)r * DD + k0) =
        make_uint4(w[0]|(w[1]<<16), w[2]|(w[3]<<16), w[4]|(w[5]<<16), w[6]|(w[7]<<16));
}

// ---------------- GEMM + fused gate epilogue + per-wm chunk summary ----------
// (frozen: round-7 proven configuration)
__global__ void __launch_bounds__(256, 2)
gemm_mma(const float* __restrict__ bias_d, const float* __restrict__ bias_v)
{
    extern __shared__ __align__(1024) char smem[];
    const uint32_t sb = smem_u32(smem);
    const int tid = threadIdx.x;
    const int nt = blockIdx.x, mt = blockIdx.y;
    const int m0 = mt * BM;

    const char* gA = (const char*)(g_A + (size_t)m0 * DD);
    const char* gB = (const char*)(g_B + (size_t)nt * BN * DD);

    // ---- loader: SW128 XOR swizzle; 4 x 16B per thread per buffer ----
    auto load_stage = [&](int s, int c) {
        uint32_t st = sb + s * STAGE_BYTES;
        #pragma unroll
        for (int i = 0; i < 4; i++) {
            int uid = i * 256 + tid;           // 0..1023
            int row = uid >> 3, u = uid & 7;
            uint32_t phys = (uint32_t)(row * 128 + (((u ^ (row & 7)) << 4)));
            size_t gofs = (size_t)row * (DD * 2) + (size_t)c * 128 + (size_t)u * 16;
            cp16(st + BUF_A + phys, gA + gofs);
            cp16(st + BUF_B + phys, gB + gofs);
        }
    };

    // ---- compute mapping: 8 warps in 2(m) x 4(n); warp tile 64x32 ----
    const int lane = tid & 31, wid = tid >> 5;
    const int wm = wid >> 2, wn = wid & 3;

    const int arow  = lane & 15;
    const int ahalf = lane >> 4;
    const int brow  = (lane & 7) | (((lane >> 4) & 1) << 3);
    const int bhalf = (lane >> 3) & 1;
    const int swA   = arow & 7;
    const int swB   = brow & 7;

    uint32_t aRowOff[4], bRowOff[2];
    #pragma unroll
    for (int mf = 0; mf < 4; mf++) aRowOff[mf] = (uint32_t)((wm * 64 + mf * 16 + arow) * 128);
    #pragma unroll
    for (int np = 0; np < 2; np++) bRowOff[np] = (uint32_t)((wn * 32 + np * 16 + brow) * 128);

    float acc[4][4][4] = {};

    load_stage(0, 0); cp_commit();
    load_stage(1, 1); cp_commit();
    load_stage(2, 2); cp_commit();

    #pragma unroll 1
    for (int c = 0; c < NKC; c++) {
        cp_wait<2>();
        __syncthreads();

        const int s = c % S_STAGES;
        const uint32_t st = sb + s * STAGE_BYTES;
        #pragma unroll
        for (int kk = 0; kk < 4; kk++) {
            const uint32_t aun = (uint32_t)(((kk * 2 + ahalf) ^ swA) << 4);
            const uint32_t bun = (uint32_t)(((kk * 2 + bhalf) ^ swB) << 4);
            uint32_t ah[4][4], bh[4][2];
            #pragma unroll
            for (int mf = 0; mf < 4; mf++)
                ldsm4(ah[mf], st + BUF_A + aRowOff[mf] + aun);
            #pragma unroll
            for (int np = 0; np < 2; np++) {
                uint32_t r[4];
                ldsm4(r, st + BUF_B + bRowOff[np] + bun);
                bh[np*2+0][0] = r[0]; bh[np*2+0][1] = r[1];
                bh[np*2+1][0] = r[2]; bh[np*2+1][1] = r[3];
            }
            #pragma unroll
            for (int mf = 0; mf < 4; mf++)
                #pragma unroll
                for (int nf = 0; nf < 4; nf++)
                    mma16816(acc[mf][nf], ah[mf], bh[nf]);
        }
        __syncthreads();
        if (c + 3 < NKC) { load_stage(s, c + 3); }
        cp_commit();
    }

    // ==== fused epilogue ====
    const int dbase = nt * 64 + wn * 16 + (lane & 3);
    const int j = lane >> 2;
    uint32_t* __restrict__ wab =
        g_ab + ((((size_t)(mt * 16 + nt) * 2 + wm) * 4 + wn) * 1024) + lane;

    #pragma unroll
    for (int nf = 0; nf < 4; nf++) {
        const int dg = dbase + nf * 4;
        const float bd = bias_d[dg];
        const float bv = bias_v[dg];

        float Ca = 1.0f, Cb = 0.0f;          // running chunk (64 t) composition
        #pragma unroll
        for (int mf = 0; mf < 4; mf++) {
            #pragma unroll
            for (int p = 0; p < 2; p++) {    // (mf,p) ascending == t ascending
                float dh = acc[mf][nf][p*2+0] + bd;
                float vh = acc[mf][nf][p*2+1] + bv;
                float del = fast_sigmoid(dh);
                float a = 1.0f - del;
                float b = del * vh;
                __half2 h = __floats2half2_rn(a, b);
                wab[(((nf * 4 + mf) * 2 + p) << 5)] = *(uint32_t*)&h;  // coalesced
                // ordered butterfly over j (lane bits 2..4): product of 8 t's
                float Wa = a, Wb = b;
                #pragma unroll
                for (int mk = 4; mk <= 16; mk <<= 1) {
                    float oa = __shfl_xor_sync(0xffffffffu, Wa, mk);
                    float ob = __shfl_xor_sync(0xffffffffu, Wb, mk);
                    if (lane & mk) {         // self upper: self ∘ other
                        Wb = fmaf(Wa, ob, Wb);
                        Wa = Wa * oa;
                    } else {                 // other upper: other ∘ self
                        Wb = fmaf(oa, Wb, ob);
                        Wa = oa * Wa;
                    }
                }
                Cb = fmaf(Wa, Cb, Wb);
                Ca = Wa * Ca;
            }
        }
        if (j == 0)                          // lanes 0..3 publish dd 0..3
            g_AS[mt * 2 + wm][dg] = make_float2(Ca, Cb);
    }
}

// ---------------- scan: fused carry-prefix + chunk replay (R12 champion) -----
// grid (NCHB, BB, 4) x 128 threads: each CTA owns 256 d-channels of one chunk.
// out stores use evict-first (__stcs): terminal stream, never re-read; keeps
// L2 for the concurrently-streamed g_ab reads and resident g_AS.
__global__ __launch_bounds__(128) void scan_fused(float* __restrict__ out)
{
    const int x = blockIdx.x;          // chunk within batch: 0..63
    const int b = blockIdx.y;
    const int q = blockIdx.z;          // d-slice: 0..3 (256 d each)
    const int mt = b * 32 + (x >> 1), wm = x & 1;
    const int tid = threadIdx.x;       // 0..127; handles d2 = q*256 + tid*2, +1
    const int d2 = q * 256 + tid * 2;
    const int ntp = d2 >> 6, rem = d2 & 63;
    const int wnp = rem >> 4, nfp = (rem >> 2) & 3, lo = rem & 3;   // lo in {0,2}

    // ---- carry-in: prefix-apply maps 0..x-1 of this batch ----
    float2 cur = make_float2(0.f, 0.f);
    {
        const int ch0 = b * NCHB;
        int c = 0;
        for (; c + 8 <= x; c += 8) {           // group-prefetch, MLP=8
            float4 m[8];
            #pragma unroll
            for (int k = 0; k < 8; k++)
                m[k] = *(const float4*)&g_AS[ch0 + c + k][d2];
            #pragma unroll
            for (int k = 0; k < 8; k++) {
                cur.x = fmaf(m[k].x, cur.x, m[k].y);
                cur.y = fmaf(m[k].z, cur.y, m[k].w);
            }
        }
        for (; c < x; c++) {                   // tail (<8)
            float4 m = *(const float4*)&g_AS[ch0 + c][d2];
            cur.x = fmaf(m.x, cur.x, m.y);
            cur.y = fmaf(m.z, cur.y, m.w);
        }
    }

    // ---- replay this chunk (double-buffered g_ab stream) ----
    const uint32_t* __restrict__ tb =
        g_ab + (((((size_t)(mt * 16 + ntp) * 2 + wm) * 4 + wnp) * 4 + nfp) * 256) + lo;
    const size_t obase = ((size_t)mt * BM + (size_t)wm * 64) * DD + d2;

    uint2 cbuf[8], nbuf[8];
    #pragma unroll
    for (int jj = 0; jj < 8; jj++) cbuf[jj] = *(const uint2*)(tb + jj * 4);

    #pragma unroll
    for (int g = 0; g < 8; g++) {              // segment g = (mf*2+p)
        if (g < 7) {
            const uint32_t* seg = tb + (g + 1) * 32;
            #pragma unroll
            for (int jj = 0; jj < 8; jj++) nbuf[jj] = *(const uint2*)(seg + jj * 4);
        }
        float* op = out + obase + (size_t)(g * 8) * DD;
        #pragma unroll
        for (int jj = 0; jj < 8; jj++) {
            float2 p0 = __half22float2(*(__half2*)&cbuf[jj].x);
            float2 p1 = __half22float2(*(__half2*)&cbuf[jj].y);
            cur.x = fmaf(p0.x, cur.x, p0.y);
            cur.y = fmaf(p1.x, cur.y, p1.y);
            __stcs((float2*)(op + (size_t)jj * DD), cur);
        }
        #pragma unroll
        for (int jj = 0; jj < 8; jj++) cbuf[jj] = nbuf[jj];
    }
}

// ---------------- launch ----------------
extern "C" void kernel_launch(void* const* d_in, const int* in_sizes, int n_in,
                              void* d_out, int out_size)
{
    const float* seq = (const float*)d_in[0];
    const float* Wd  = (const float*)d_in[1];
    const float* bd  = (const float*)d_in[2];
    const float* Wv  = (const float*)d_in[3];
    const float* bv  = (const float*)d_in[4];
    float* out = (float*)d_out;

    cudaFuncSetAttribute(gemm_mma, cudaFuncAttributeMaxDynamicSharedMemorySize, SMEM_TOTAL);

    conv_A<<<16384, 256>>>(seq);
    conv_B<<<1024, 256>>>(Wd, Wv);
    gemm_mma<<<dim3(NT, MT), 256, SMEM_TOTAL>>>(bd, bv);
    scan_fused<<<dim3(NCHB, BB, 4), 128>>>(out);
}